// round 3
// baseline (speedup 1.0000x reference)
#include <cuda_runtime.h>

#define N_MAT 50000
#define N_EDGE 800000
#define D 64
#define NB_SCAN 196   // ceil(N_MAT/256)

// ---------------- scratch (static device memory; no allocations) ----------------
__device__ __align__(16) float g_h[N_MAT * D];       // node embeddings h
__device__ __align__(16) float g_Y[N_MAT * D];       // sum_e exp_e * X_e per dst (unnormalized)
__device__ float g_d[N_MAT];                         // h[n] . a_cross[:64]
__device__ float g_p[N_MAT];                         // operations[op] . b[:48]
__device__ float g_expself[N_MAT];                   // exp(self score)
__device__ float g_expcross[N_EDGE];                 // exp(cross score)
__device__ float g_b[D];                             // b = W_op^T a_cross[64:]
__device__ float g_sum;                              // softmax denominator
// CSR-by-dst scratch
__device__ int g_cnt[N_MAT];
__device__ int g_start[N_MAT];
__device__ int g_cur[N_MAT];
__device__ int g_part[NB_SCAN];
__device__ __align__(16) uint4 g_csr[N_EDGE];        // {eid, src, bits(exp), 0}

__device__ __forceinline__ float warp_sum(float v) {
#pragma unroll
    for (int o = 16; o; o >>= 1) v += __shfl_xor_sync(0xffffffffu, v, o);
    return v;
}

// ---------------- K0: zero counts, reset sum, compute b ----------------
__global__ void k_init(const float* __restrict__ W_op, const float* __restrict__ a_cross) {
    int idx = blockIdx.x * blockDim.x + threadIdx.x;
    int stride = gridDim.x * blockDim.x;
    for (int i = idx; i < N_MAT; i += stride) g_cnt[i] = 0;
    if (blockIdx.x == 0) {
        if (threadIdx.x < D) {
            float bb = 0.f;
#pragma unroll
            for (int c = 0; c < D; c++) bb += a_cross[D + c] * W_op[c * D + threadIdx.x];
            g_b[threadIdx.x] = bb;
        }
        if (threadIdx.x == D) g_sum = 0.f;
    }
}

// ---------------- K1: h = materials @ W_mat^T, d, self scores + exp partial sum ----
__global__ void __launch_bounds__(256) k_nodes(const float* __restrict__ mat,
                                               const float* __restrict__ W_mat,
                                               const float* __restrict__ a_self,
                                               const float* __restrict__ a_cross) {
    __shared__ float wt[64 * 65];   // wt[k][c] = W_mat[c][k], padded
    __shared__ float ac1[64], asc[64];
    __shared__ float spart[8];
    int tid = threadIdx.x;
    for (int e = tid; e < 4096; e += 256) {
        int c = e >> 6, k = e & 63;
        wt[k * 65 + c] = W_mat[e];
    }
    if (tid < 64) { ac1[tid] = a_cross[tid]; asc[tid] = a_self[tid] + a_self[64 + tid]; }
    __syncthreads();

    int warp = tid >> 5, lane = tid & 31;
    int row = blockIdx.x * 8 + warp;   // grid exact: 6250*8 = 50000
    float r0 = mat[row * 64 + lane];
    float r1 = mat[row * 64 + 32 + lane];
    float acc0 = 0.f, acc1 = 0.f;
#pragma unroll
    for (int k = 0; k < 64; k++) {
        float xk = __shfl_sync(0xffffffffu, (k < 32) ? r0 : r1, k & 31);
        acc0 += xk * wt[k * 65 + lane];
        acc1 += xk * wt[k * 65 + 32 + lane];
    }
    g_h[row * 64 + lane] = acc0;
    g_h[row * 64 + 32 + lane] = acc1;

    float dv = warp_sum(acc0 * ac1[lane] + acc1 * ac1[32 + lane]);
    float sv = warp_sum(acc0 * asc[lane] + acc1 * asc[32 + lane]);
    if (lane == 0) {
        g_d[row] = dv;
        float s = sv > 0.f ? sv : 0.2f * sv;        // leaky_relu(0.2)
        float ex = __expf(s);
        g_expself[row] = ex;
        spart[warp] = ex;
    }
    __syncthreads();
    if (tid == 0) {
        float t = 0.f;
#pragma unroll
        for (int i = 0; i < 8; i++) t += spart[i];
        atomicAdd(&g_sum, t);
    }
}

// ---------------- K2: p[op] = operations[op] . b[:48] ----------------
__global__ void __launch_bounds__(256) k_pops(const float* __restrict__ ops) {
    __shared__ float bs[48];
    int tid = threadIdx.x;
    if (tid < 48) bs[tid] = g_b[tid];
    __syncthreads();
    int op = blockIdx.x * 16 + (tid >> 4);   // grid exact: 3125*16 = 50000
    int j = tid & 15;
    const float* r = ops + op * 48;
    float v = r[j] * bs[j] + r[16 + j] * bs[16 + j] + r[32 + j] * bs[32 + j];
#pragma unroll
    for (int o = 8; o; o >>= 1) v += __shfl_xor_sync(0xffffffffu, v, o);
    if (j == 0) g_p[op] = v;
}

// ---------------- K3: cross scores + exp partial sum + dst degree count ----------
__global__ void __launch_bounds__(256) k_escore(const float* __restrict__ ea,
                                                const int* __restrict__ ei) {
    __shared__ float b16[16];
    __shared__ float spart[8];
    int tid = threadIdx.x;
    if (tid < 16) b16[tid] = g_b[48 + tid];
    __syncthreads();
    int e = blockIdx.x * 256 + tid;          // grid exact: 3125*256 = 800000
    int src = ei[e];
    int dst = ei[N_EDGE + e];
    const float4* ea4 = (const float4*)ea;
    float s = g_d[dst] + g_p[src];
#pragma unroll
    for (int q = 0; q < 4; q++) {
        float4 v = ea4[e * 4 + q];
        s += v.x * b16[4 * q] + v.y * b16[4 * q + 1] + v.z * b16[4 * q + 2] + v.w * b16[4 * q + 3];
    }
    s = s > 0.f ? s : 0.2f * s;
    float ex = __expf(s);
    g_expcross[e] = ex;
    atomicAdd(&g_cnt[dst], 1);               // degree count (RED, no return)
    float wsum = warp_sum(ex);
    if ((tid & 31) == 0) spart[tid >> 5] = wsum;
    __syncthreads();
    if (tid == 0) {
        float t = 0.f;
#pragma unroll
        for (int i = 0; i < 8; i++) t += spart[i];
        atomicAdd(&g_sum, t);
    }
}

// ---------------- scan: exclusive prefix sum of g_cnt -> g_start ----------------
__global__ void k_scan1() {
    __shared__ int s[256];
    int tid = threadIdx.x;
    int i = blockIdx.x * 256 + tid;
    int v = (i < N_MAT) ? g_cnt[i] : 0;
    s[tid] = v;
    __syncthreads();
#pragma unroll
    for (int o = 1; o < 256; o <<= 1) {
        int t = (tid >= o) ? s[tid - o] : 0;
        __syncthreads();
        if (tid >= o) s[tid] += t;
        __syncthreads();
    }
    if (i < N_MAT) g_start[i] = s[tid] - v;     // block-local exclusive
    if (tid == 255) g_part[blockIdx.x] = s[255];
}

__global__ void k_scan2() {
    __shared__ int s[256];
    int tid = threadIdx.x;
    int v = (tid < NB_SCAN) ? g_part[tid] : 0;
    s[tid] = v;
    __syncthreads();
#pragma unroll
    for (int o = 1; o < 256; o <<= 1) {
        int t = (tid >= o) ? s[tid - o] : 0;
        __syncthreads();
        if (tid >= o) s[tid] += t;
        __syncthreads();
    }
    if (tid < NB_SCAN) g_part[tid] = s[tid] - v;  // exclusive block offsets
}

__global__ void k_scan3() {
    int i = blockIdx.x * 256 + threadIdx.x;
    if (i < N_MAT) {
        int st = g_start[i] + g_part[i >> 8];
        g_start[i] = st;
        g_cur[i] = st;
    }
}

// ---------------- fill: scatter edges into CSR order ----------------
__global__ void __launch_bounds__(256) k_fill(const int* __restrict__ ei) {
    int e = blockIdx.x * 256 + threadIdx.x;   // 3125 blocks
    int src = ei[e];
    int dst = ei[N_EDGE + e];
    float w = g_expcross[e];
    int pos = atomicAdd(&g_cur[dst], 1);
    g_csr[pos] = make_uint4((unsigned)e, (unsigned)src, __float_as_uint(w), 0u);
}

// ---------------- segmented accumulate: Y[n] = sum_{e in seg(n)} w_e * X_e ------
__global__ void __launch_bounds__(256) k_accum_csr(const float* __restrict__ ops,
                                                   const float* __restrict__ ea) {
    int tid = threadIdx.x;
    int row = blockIdx.x * 16 + (tid >> 4);   // grid exact: 3125*16 = 50000
    int j = tid & 15;                         // 16 lanes x float4 = 64 components
    int beg = g_start[row];
    int cnt = g_cnt[row];
    const float4* ea4 = (const float4*)ea;
    float4 acc = make_float4(0.f, 0.f, 0.f, 0.f);
#pragma unroll 2
    for (int i = 0; i < cnt; i++) {
        uint4 ent = g_csr[beg + i];           // broadcast within half-warp
        float w = __uint_as_float(ent.z);
        float4 v;
        if (j < 12) v = ((const float4*)(ops + ent.y * 48))[j];     // comps 0..47
        else        v = ea4[ent.x * 4 + (j - 12)];                   // comps 48..63
        acc.x += w * v.x; acc.y += w * v.y; acc.z += w * v.z; acc.w += w * v.w;
    }
    ((float4*)(g_Y + row * 64))[j] = acc;     // single plain store, no atomics
}

// ---------------- K5: out = elu(norm_self*h + (1/S) * Y @ W_op^T) ----------------
__global__ void __launch_bounds__(256) k_final(const float* __restrict__ W_op,
                                               float* __restrict__ out) {
    __shared__ float wt[64 * 65];   // wt[k][c] = W_op[c][k]
    __shared__ float s_inv_sh;
    int tid = threadIdx.x;
    for (int e = tid; e < 4096; e += 256) {
        int c = e >> 6, k = e & 63;
        wt[k * 65 + c] = W_op[e];
    }
    if (tid == 0) s_inv_sh = 1.0f / g_sum;
    __syncthreads();
    float s_inv = s_inv_sh;

    int warp = tid >> 5, lane = tid & 31;
    int row = blockIdx.x * 8 + warp;
    float r0 = g_Y[row * 64 + lane];
    float r1 = g_Y[row * 64 + 32 + lane];
    float acc0 = 0.f, acc1 = 0.f;
#pragma unroll
    for (int k = 0; k < 64; k++) {
        float yk = __shfl_sync(0xffffffffu, (k < 32) ? r0 : r1, k & 31);
        acc0 += yk * wt[k * 65 + lane];
        acc1 += yk * wt[k * 65 + 32 + lane];
    }
    float ns = g_expself[row] * s_inv;
    float o0 = ns * g_h[row * 64 + lane] + s_inv * acc0;
    float o1 = ns * g_h[row * 64 + 32 + lane] + s_inv * acc1;
    o0 = o0 > 0.f ? o0 : expm1f(o0);   // elu(alpha=1)
    o1 = o1 > 0.f ? o1 : expm1f(o1);
    out[row * 64 + lane] = o0;
    out[row * 64 + 32 + lane] = o1;
}

extern "C" void kernel_launch(void* const* d_in, const int* in_sizes, int n_in,
                              void* d_out, int out_size) {
    const float* materials  = (const float*)d_in[0];
    const float* operations = (const float*)d_in[1];
    const float* edge_attr  = (const float*)d_in[2];
    const int*   edge_index = (const int*)d_in[3];
    const float* W_mat      = (const float*)d_in[4];
    const float* W_op       = (const float*)d_in[5];
    const float* a_self     = (const float*)d_in[6];
    const float* a_cross    = (const float*)d_in[7];
    float* out = (float*)d_out;

    k_init     <<<256, 256>>>(W_op, a_cross);
    k_nodes    <<<N_MAT / 8, 256>>>(materials, W_mat, a_self, a_cross);
    k_pops     <<<N_MAT / 16, 256>>>(operations);
    k_escore   <<<N_EDGE / 256, 256>>>(edge_attr, edge_index);
    k_scan1    <<<NB_SCAN, 256>>>();
    k_scan2    <<<1, 256>>>();
    k_scan3    <<<NB_SCAN, 256>>>();
    k_fill     <<<N_EDGE / 256, 256>>>(edge_index);
    k_accum_csr<<<N_MAT / 16, 256>>>(operations, edge_attr);
    k_final    <<<N_MAT / 8, 256>>>(W_op, out);
}

// round 4
// speedup vs baseline: 1.3265x; 1.3265x over previous
#include <cuda_runtime.h>

#define N_MAT 50000
#define N_EDGE 800000
#define D 64
#define NB_SCAN 196   // ceil(N_MAT/256)

// ---------------- scratch (static device memory; no allocations) ----------------
__device__ __align__(16) float g_h[N_MAT * D];
__device__ __align__(16) float g_Y[N_MAT * D];
__device__ float g_d[N_MAT];
__device__ float g_p[N_MAT];
__device__ float g_expself[N_MAT];
__device__ float g_expcross[N_EDGE];
__device__ float g_b[D];
__device__ float g_sum;
__device__ int g_cnt[N_MAT];
__device__ int g_start[N_MAT];
__device__ int g_cur[N_MAT];
__device__ int g_part[NB_SCAN];
__device__ __align__(16) uint4 g_csr[N_EDGE];   // {eid, src, bits(exp), 0}

__device__ __forceinline__ float warp_sum(float v) {
#pragma unroll
    for (int o = 16; o; o >>= 1) v += __shfl_xor_sync(0xffffffffu, v, o);
    return v;
}

// ---------------- K0: zero counts, reset sum, compute b = W_op^T a_cross[64:] ----
__global__ void k_init(const float* __restrict__ W_op, const float* __restrict__ a_cross) {
    int idx = blockIdx.x * blockDim.x + threadIdx.x;
    int stride = gridDim.x * blockDim.x;
    for (int i = idx; i < N_MAT; i += stride) g_cnt[i] = 0;
    if (blockIdx.x == 0) {
        if (threadIdx.x < D) {
            float bb = 0.f;
#pragma unroll
            for (int c = 0; c < D; c++) bb += a_cross[D + c] * W_op[c * D + threadIdx.x];
            g_b[threadIdx.x] = bb;
        }
        if (threadIdx.x == D) g_sum = 0.f;
    }
}

// ---------------- K1: register-tiled h = mat @ W_mat^T + d + self-score ---------
__global__ void __launch_bounds__(256) k_nodes(const float* __restrict__ mat,
                                               const float* __restrict__ W_mat,
                                               const float* __restrict__ a_self,
                                               const float* __restrict__ a_cross) {
    __shared__ float m[64 * 68];    // m[r][k], stride 68 (16B-aligned rows)
    __shared__ float wt[64 * 68];   // wt[k][c] = W_mat[c][k]
    __shared__ float ac1[64], asc[64];
    __shared__ float s_ex[16];
    int tid = threadIdx.x;
    for (int e = tid; e < 4096; e += 256)
        wt[(e & 63) * 68 + (e >> 6)] = W_mat[e];
    if (tid < 64) { ac1[tid] = a_cross[tid]; asc[tid] = a_self[tid] + a_self[64 + tid]; }
    int rowbase = blockIdx.x * 64;
    const float4* mat4 = (const float4*)mat;
#pragma unroll
    for (int q = 0; q < 4; q++) {
        int fi = q * 256 + tid;                 // local float4 index 0..1023
        int gfi = rowbase * 16 + fi;
        float4 v = (gfi < N_MAT * 16) ? mat4[gfi] : make_float4(0.f, 0.f, 0.f, 0.f);
        *(float4*)&m[(fi >> 4) * 68 + (fi & 15) * 4] = v;
    }
    __syncthreads();

    int cr = tid & 15, rr = tid >> 4;
    int c0 = cr * 4, r0 = rr * 4;
    float4 acc[4];
#pragma unroll
    for (int r = 0; r < 4; r++) acc[r] = make_float4(0.f, 0.f, 0.f, 0.f);
#pragma unroll
    for (int kk = 0; kk < 16; kk++) {
        float4 b0 = *(float4*)&wt[(kk * 4 + 0) * 68 + c0];
        float4 b1 = *(float4*)&wt[(kk * 4 + 1) * 68 + c0];
        float4 b2 = *(float4*)&wt[(kk * 4 + 2) * 68 + c0];
        float4 b3 = *(float4*)&wt[(kk * 4 + 3) * 68 + c0];
#pragma unroll
        for (int r = 0; r < 4; r++) {
            float4 a = *(float4*)&m[(r0 + r) * 68 + kk * 4];
            acc[r].x += a.x * b0.x + a.y * b1.x + a.z * b2.x + a.w * b3.x;
            acc[r].y += a.x * b0.y + a.y * b1.y + a.z * b2.y + a.w * b3.y;
            acc[r].z += a.x * b0.z + a.y * b1.z + a.z * b2.z + a.w * b3.z;
            acc[r].w += a.x * b0.w + a.y * b1.w + a.z * b2.w + a.w * b3.w;
        }
    }
    unsigned hmask = 0xFFFFu << ((tid & 31) & 16);
    float4 a1 = *(float4*)&ac1[c0];
    float4 as = *(float4*)&asc[c0];
    float exl = 0.f;
#pragma unroll
    for (int r = 0; r < 4; r++) {
        int row = rowbase + r0 + r;
        bool valid = row < N_MAT;
        if (valid) *(float4*)&g_h[row * 64 + c0] = acc[r];
        float dv = acc[r].x * a1.x + acc[r].y * a1.y + acc[r].z * a1.z + acc[r].w * a1.w;
        float sv = acc[r].x * as.x + acc[r].y * as.y + acc[r].z * as.z + acc[r].w * as.w;
#pragma unroll
        for (int o = 8; o; o >>= 1) {
            dv += __shfl_xor_sync(hmask, dv, o, 16);
            sv += __shfl_xor_sync(hmask, sv, o, 16);
        }
        if (cr == 0 && valid) {
            g_d[row] = dv;
            float s = sv > 0.f ? sv : 0.2f * sv;
            float ex = __expf(s);
            g_expself[row] = ex;
            exl += ex;
        }
    }
    if (cr == 0) s_ex[rr] = exl;
    __syncthreads();
    if (tid == 0) {
        float t = 0.f;
#pragma unroll
        for (int i = 0; i < 16; i++) t += s_ex[i];
        atomicAdd(&g_sum, t);
    }
}

// ---------------- K2: p[op] = operations[op] . b[:48] ----------------
__global__ void __launch_bounds__(256) k_pops(const float* __restrict__ ops) {
    __shared__ float bs[48];
    int tid = threadIdx.x;
    if (tid < 48) bs[tid] = g_b[tid];
    __syncthreads();
    int op = blockIdx.x * 16 + (tid >> 4);
    int j = tid & 15;
    const float* r = ops + op * 48;
    float v = r[j] * bs[j] + r[16 + j] * bs[16 + j] + r[32 + j] * bs[32 + j];
#pragma unroll
    for (int o = 8; o; o >>= 1) v += __shfl_xor_sync(0xffffffffu, v, o);
    if (j == 0) g_p[op] = v;
}

// ---------------- K3: cross scores (2 edges/thread) + degree count ---------------
__global__ void __launch_bounds__(256) k_escore(const float* __restrict__ ea,
                                                const int* __restrict__ ei) {
    __shared__ float b16[16];
    __shared__ float spart[8];
    int tid = threadIdx.x;
    if (tid < 16) b16[tid] = g_b[48 + tid];
    __syncthreads();
    const float4* ea4 = (const float4*)ea;
    float exs = 0.f;
    int base = blockIdx.x * 512 + tid;
#pragma unroll
    for (int u = 0; u < 2; u++) {
        int e = base + u * 256;
        if (e < N_EDGE) {
            int src = ei[e];
            int dst = ei[N_EDGE + e];
            float s = g_d[dst] + g_p[src];
#pragma unroll
            for (int q = 0; q < 4; q++) {
                float4 v = ea4[e * 4 + q];
                s += v.x * b16[4 * q] + v.y * b16[4 * q + 1] + v.z * b16[4 * q + 2] + v.w * b16[4 * q + 3];
            }
            s = s > 0.f ? s : 0.2f * s;
            float ex = __expf(s);
            g_expcross[e] = ex;
            atomicAdd(&g_cnt[dst], 1);
            exs += ex;
        }
    }
    float wsum = warp_sum(exs);
    if ((tid & 31) == 0) spart[tid >> 5] = wsum;
    __syncthreads();
    if (tid == 0) {
        float t = 0.f;
#pragma unroll
        for (int i = 0; i < 8; i++) t += spart[i];
        atomicAdd(&g_sum, t);
    }
}

// ---------------- scan: exclusive prefix sum of g_cnt -> g_start ----------------
__global__ void k_scan1() {
    __shared__ int s[256];
    int tid = threadIdx.x;
    int i = blockIdx.x * 256 + tid;
    int v = (i < N_MAT) ? g_cnt[i] : 0;
    s[tid] = v;
    __syncthreads();
#pragma unroll
    for (int o = 1; o < 256; o <<= 1) {
        int t = (tid >= o) ? s[tid - o] : 0;
        __syncthreads();
        if (tid >= o) s[tid] += t;
        __syncthreads();
    }
    if (i < N_MAT) g_start[i] = s[tid] - v;
    if (tid == 255) g_part[blockIdx.x] = s[255];
}

__global__ void k_scan2() {
    __shared__ int s[256];
    int tid = threadIdx.x;
    int v = (tid < NB_SCAN) ? g_part[tid] : 0;
    s[tid] = v;
    __syncthreads();
#pragma unroll
    for (int o = 1; o < 256; o <<= 1) {
        int t = (tid >= o) ? s[tid - o] : 0;
        __syncthreads();
        if (tid >= o) s[tid] += t;
        __syncthreads();
    }
    if (tid < NB_SCAN) g_part[tid] = s[tid] - v;
}

__global__ void k_scan3() {
    int i = blockIdx.x * 256 + threadIdx.x;
    if (i < N_MAT) {
        int st = g_start[i] + g_part[i >> 8];
        g_start[i] = st;
        g_cur[i] = st;
    }
}

// ---------------- fill: scatter edges into CSR order ----------------
__global__ void __launch_bounds__(256) k_fill(const int* __restrict__ ei) {
    int e = blockIdx.x * 256 + threadIdx.x;
    int src = ei[e];
    int dst = ei[N_EDGE + e];
    float w = g_expcross[e];
    int pos = atomicAdd(&g_cur[dst], 1);
    g_csr[pos] = make_uint4((unsigned)e, (unsigned)src, __float_as_uint(w), 0u);
}

// -------- segmented accumulate: coalesced entry loads + shfl distribution -------
__global__ void __launch_bounds__(256) k_accum_csr(const float* __restrict__ ops,
                                                   const float* __restrict__ ea) {
    int tid = threadIdx.x;
    int row = blockIdx.x * 16 + (tid >> 4);
    int j = tid & 15;
    unsigned hmask = 0xFFFFu << ((tid & 31) & 16);
    int beg = g_start[row];
    int cnt = g_cnt[row];
    const float4* ea4 = (const float4*)ea;
    const float4* ops4 = (const float4*)ops;
    float4 acc = make_float4(0.f, 0.f, 0.f, 0.f);
    for (int base = 0; base < cnt; base += 16) {
        int rem = cnt - base;
        int nb = rem < 16 ? rem : 16;
        uint4 ent = (j < nb) ? g_csr[beg + base + j] : make_uint4(0u, 0u, 0u, 0u);
#pragma unroll 8
        for (int i = 0; i < nb; i++) {
            unsigned eid = __shfl_sync(hmask, ent.x, i, 16);
            unsigned src = __shfl_sync(hmask, ent.y, i, 16);
            float w = __uint_as_float(__shfl_sync(hmask, ent.z, i, 16));
            float4 v = (j < 12) ? ops4[src * 12 + j] : ea4[eid * 4 + (j - 12)];
            acc.x += w * v.x; acc.y += w * v.y; acc.z += w * v.z; acc.w += w * v.w;
        }
    }
    ((float4*)(g_Y + row * 64))[j] = acc;
}

// ---------------- K5: register-tiled out = elu(ns*h + s_inv * Y @ W_op^T) -------
__global__ void __launch_bounds__(256) k_final(const float* __restrict__ W_op,
                                               float* __restrict__ out) {
    __shared__ float m[64 * 68];    // Y tile
    __shared__ float wt[64 * 68];   // wt[k][c] = W_op[c][k]
    __shared__ float s_inv_sh;
    int tid = threadIdx.x;
    for (int e = tid; e < 4096; e += 256)
        wt[(e & 63) * 68 + (e >> 6)] = W_op[e];
    if (tid == 0) s_inv_sh = 1.0f / g_sum;
    int rowbase = blockIdx.x * 64;
    const float4* Y4 = (const float4*)g_Y;
#pragma unroll
    for (int q = 0; q < 4; q++) {
        int fi = q * 256 + tid;
        int gfi = rowbase * 16 + fi;
        float4 v = (gfi < N_MAT * 16) ? Y4[gfi] : make_float4(0.f, 0.f, 0.f, 0.f);
        *(float4*)&m[(fi >> 4) * 68 + (fi & 15) * 4] = v;
    }
    __syncthreads();
    float s_inv = s_inv_sh;

    int cr = tid & 15, rr = tid >> 4;
    int c0 = cr * 4, r0 = rr * 4;
    float4 acc[4];
#pragma unroll
    for (int r = 0; r < 4; r++) acc[r] = make_float4(0.f, 0.f, 0.f, 0.f);
#pragma unroll
    for (int kk = 0; kk < 16; kk++) {
        float4 b0 = *(float4*)&wt[(kk * 4 + 0) * 68 + c0];
        float4 b1 = *(float4*)&wt[(kk * 4 + 1) * 68 + c0];
        float4 b2 = *(float4*)&wt[(kk * 4 + 2) * 68 + c0];
        float4 b3 = *(float4*)&wt[(kk * 4 + 3) * 68 + c0];
#pragma unroll
        for (int r = 0; r < 4; r++) {
            float4 a = *(float4*)&m[(r0 + r) * 68 + kk * 4];
            acc[r].x += a.x * b0.x + a.y * b1.x + a.z * b2.x + a.w * b3.x;
            acc[r].y += a.x * b0.y + a.y * b1.y + a.z * b2.y + a.w * b3.y;
            acc[r].z += a.x * b0.z + a.y * b1.z + a.z * b2.z + a.w * b3.z;
            acc[r].w += a.x * b0.w + a.y * b1.w + a.z * b2.w + a.w * b3.w;
        }
    }
#pragma unroll
    for (int r = 0; r < 4; r++) {
        int row = rowbase + r0 + r;
        if (row < N_MAT) {
            float ns = g_expself[row] * s_inv;
            float4 h4 = *(const float4*)&g_h[row * 64 + c0];
            float4 o;
            o.x = ns * h4.x + s_inv * acc[r].x;
            o.y = ns * h4.y + s_inv * acc[r].y;
            o.z = ns * h4.z + s_inv * acc[r].z;
            o.w = ns * h4.w + s_inv * acc[r].w;
            o.x = o.x > 0.f ? o.x : expm1f(o.x);
            o.y = o.y > 0.f ? o.y : expm1f(o.y);
            o.z = o.z > 0.f ? o.z : expm1f(o.z);
            o.w = o.w > 0.f ? o.w : expm1f(o.w);
            *(float4*)&out[row * 64 + c0] = o;
        }
    }
}

extern "C" void kernel_launch(void* const* d_in, const int* in_sizes, int n_in,
                              void* d_out, int out_size) {
    const float* materials  = (const float*)d_in[0];
    const float* operations = (const float*)d_in[1];
    const float* edge_attr  = (const float*)d_in[2];
    const int*   edge_index = (const int*)d_in[3];
    const float* W_mat      = (const float*)d_in[4];
    const float* W_op       = (const float*)d_in[5];
    const float* a_self     = (const float*)d_in[6];
    const float* a_cross    = (const float*)d_in[7];
    float* out = (float*)d_out;

    k_init     <<<256, 256>>>(W_op, a_cross);
    k_nodes    <<<(N_MAT + 63) / 64, 256>>>(materials, W_mat, a_self, a_cross);
    k_pops     <<<N_MAT / 16, 256>>>(operations);
    k_escore   <<<(N_EDGE + 511) / 512, 256>>>(edge_attr, edge_index);
    k_scan1    <<<NB_SCAN, 256>>>();
    k_scan2    <<<1, 256>>>();
    k_scan3    <<<NB_SCAN, 256>>>();
    k_fill     <<<N_EDGE / 256, 256>>>(edge_index);
    k_accum_csr<<<N_MAT / 16, 256>>>(operations, edge_attr);
    k_final    <<<(N_MAT + 63) / 64, 256>>>(W_op, out);
}